// round 5
// baseline (speedup 1.0000x reference)
#include <cuda_runtime.h>
#include <cstdint>

// SpikeFP32Adder — integer re-implementation of the soft-gate FP32 adder.
// R5: LDG.128 loads (16 per tile instead of 64 LDG.32), nibble-deposit pack,
// 3-stage select/OR butterfly across 8-lane groups to assemble row words,
// STG.128 streaming stores. We are near the ~6.9 TB/s LTS roofline; this
// round trims issue/LSU overhead feeding it.

__device__ __forceinline__ unsigned spike_fp32_add(unsigned ra, unsigned rb) {
    const unsigned sa = ra >> 31, sb = rb >> 31;
    const unsigned ea = (ra >> 23) & 0xFFu, eb = (rb >> 23) & 0xFFu;

    const unsigned eae = ea ? ea : 1u;                      // e_eff
    const unsigned ebe = eb ? eb : 1u;
    const unsigned manta = (ra & 0x7FFFFFu) | ((ea ? 1u : 0u) << 23);
    const unsigned mantb = (rb & 0x7FFFFFu) | ((eb ? 1u : 0u) << 23);

    const bool exp_eq = (eae == ebe);
    const bool a_ge_b = (eae > ebe) || (exp_eq && (manta >= mantb));
    const bool abs_eq = exp_eq && (manta == mantb);

    const unsigned ediff = a_ge_b ? (eae - ebe) : (ebe - eae);
    const bool big = (ediff >= 24u);                        // is_big_diff
    const unsigned shift = big ? 0u : ediff;

    const unsigned emax = a_ge_b ? eae : ebe;
    const unsigned Ml  = (a_ge_b ? manta : mantb) << 4;     // 28-bit
    const unsigned Ms0 = (a_ge_b ? mantb : manta) << 4;

    const bool sticky = (Ms0 & ((1u << shift) - 1u)) != 0u;
    const unsigned Ms = Ms0 >> shift;

    const unsigned ds = sa ^ sb;                            // diff sign
    const bool exact_cancel = (ds != 0u) && abs_eq;
    const unsigned s_large = a_ge_b ? sa : sb;

    const unsigned sum = Ml + Ms;
    const unsigned diff = (Ml - Ms - ((ds && sticky) ? 1u : 0u)) & 0xFFFFFFFu;
    const unsigned res_carry = ds ? 0u : ((sum >> 28) & 1u);
    const unsigned mant_res = ds ? diff : (sum & 0xFFFFFFFu);

    const unsigned lzc = (unsigned)__clz(mant_res) - 4u;    // 0..28
    const bool underflow = (lzc >= emax);
    const unsigned norm_m = (mant_res << lzc) & 0xFFFFFFFu;

    const unsigned e_after  = (emax - lzc) & 0xFFu;
    const unsigned e_plus1  = (emax + 1u) & 0xFFu;
    const unsigned e_normal = underflow ? 0u : e_after;
    const unsigned final_e  = res_carry ? e_plus1 : e_normal;

    const unsigned m_pre = res_carry ? ((mant_res >> 5) & 0x7FFFFFu)
                                     : ((norm_m  >> 4) & 0x7FFFFFu);
    const unsigned r_pre = res_carry ? ((mant_res >> 4) & 1u)
                                     : ((norm_m  >> 3) & 1u);
    const bool st_raw = res_carry ? ((mant_res & 0xFu) != 0u)
                                  : ((norm_m  & 0x7u) != 0u);
    const bool st_pre = st_raw || ((ds == 0u) && sticky);

    const unsigned m_sel = underflow ? ((mant_res >> 5) & 0x7FFFFFu) : m_pre;
    const unsigned L = m_sel & 1u;
    const unsigned do_round =
        ((r_pre != 0u) && (st_pre || (L != 0u)) && !underflow) ? 1u : 0u;

    // Circuit quirk: round-adder carry-out is structurally 0 — mantissa wraps
    // to 0 on rounding overflow WITHOUT exponent increment.
    const unsigned m_final = (m_sel + do_round) & 0x7FFFFFu;

    const bool inf = (final_e == 0xFFu);
    unsigned cs = exact_cancel ? 0u : s_large;
    unsigned ce = exact_cancel ? 0u : final_e;
    unsigned cm = exact_cancel ? 0u : m_final;
    cs = inf ? s_large : cs;
    ce = inf ? 0xFFu   : ce;
    cm = inf ? 0u      : cm;

    const unsigned normal = (cs << 31) | (ce << 23) | cm;
    const unsigned larger = a_ge_b ? ra : rb;
    return big ? larger : normal;
}

// Extract bit-23 of 4 words (0x3F800000 or 0) into a nibble:
// bit3=x(col c0), bit2=y, bit1=z, bit0=w.
__device__ __forceinline__ unsigned nib4(uint4 v) {
    return ((v.x >> 20) & 8u) | ((v.y >> 21) & 4u) |
           ((v.z >> 22) & 2u) | ((v.w >> 23) & 1u);
}

// OR-reduce p[0..7] across each 8-lane group with a 3-stage butterfly such
// that lane k (=lane&7) of the group ends holding OR over the group of p[k].
__device__ __forceinline__ unsigned group8_or_transpose(const unsigned p[8],
                                                        unsigned lane) {
    const unsigned k = lane & 7u;
    // stage m=4: keep j-half with (j&4)==(k&4), send+OR the other
    const bool h4 = (k & 4u) != 0u;
    unsigned s0 = h4 ? p[0] : p[4];
    unsigned s1 = h4 ? p[1] : p[5];
    unsigned s2 = h4 ? p[2] : p[6];
    unsigned s3 = h4 ? p[3] : p[7];
    s0 = __shfl_xor_sync(0xFFFFFFFFu, s0, 4);
    s1 = __shfl_xor_sync(0xFFFFFFFFu, s1, 4);
    s2 = __shfl_xor_sync(0xFFFFFFFFu, s2, 4);
    s3 = __shfl_xor_sync(0xFFFFFFFFu, s3, 4);
    unsigned n0 = (h4 ? p[4] : p[0]) | s0;
    unsigned n1 = (h4 ? p[5] : p[1]) | s1;
    unsigned n2 = (h4 ? p[6] : p[2]) | s2;
    unsigned n3 = (h4 ? p[7] : p[3]) | s3;
    // stage m=2
    const bool h2 = (k & 2u) != 0u;
    unsigned t0 = h2 ? n0 : n2;
    unsigned t1 = h2 ? n1 : n3;
    t0 = __shfl_xor_sync(0xFFFFFFFFu, t0, 2);
    t1 = __shfl_xor_sync(0xFFFFFFFFu, t1, 2);
    unsigned u0 = (h2 ? n2 : n0) | t0;
    unsigned u1 = (h2 ? n3 : n1) | t1;
    // stage m=1
    const bool h1 = (k & 1u) != 0u;
    unsigned s = h1 ? u0 : u1;
    s = __shfl_xor_sync(0xFFFFFFFFu, s, 1);
    return (h1 ? u1 : u0) | s;
}

__device__ __forceinline__ void process_tile(const uint4* __restrict__ A4,
                                             const uint4* __restrict__ B4,
                                             float* __restrict__ O,
                                             int tile, unsigned lane) {
    const size_t v4base = (size_t)tile * 256;           // 1024 words / 4
    const uint4* pa = A4 + v4base + lane;
    const uint4* pb = B4 + v4base + lane;

    // Field position for this lane's 4 columns: c0=(lane&7)*4, bits [sh..sh+3],
    // column c lands at bit 31-c (IEEE layout, MSB-first columns).
    const unsigned sh = 28u - 4u * (lane & 7u);

    // Iteration j loads rows 4j..4j+3 (512B contiguous per warp-load).
    unsigned qa[8], qb[8];
    #pragma unroll
    for (int j = 0; j < 8; j++) {
        const uint4 xa = __ldg(pa + j * 32);
        const uint4 xb = __ldg(pb + j * 32);
        qa[j] = nib4(xa) << sh;
        qb[j] = nib4(xb) << sh;
    }

    // After reduce: lane 8g+k holds row (4k+g). Row r lives on lane
    // ((r&3)<<3)|(r>>2); route it to lane r.
    const unsigned va = group8_or_transpose(qa, lane);
    const unsigned vb = group8_or_transpose(qb, lane);
    const unsigned src = ((lane & 3u) << 3) | (lane >> 2);
    const unsigned ra = __shfl_sync(0xFFFFFFFFu, va, src);
    const unsigned rb = __shfl_sync(0xFFFFFFFFu, vb, src);

    const unsigned res = spike_fp32_add(ra, rb);        // per-lane row

    // Unpack: iteration i stores rows 4i..4i+3 (512B) with STG.128 streaming.
    float* po = O + (size_t)tile * 1024;
    #pragma unroll
    for (int i = 0; i < 8; i++) {
        const int rsrc = i * 4 + (lane >> 3);
        const unsigned w = __shfl_sync(0xFFFFFFFFu, res, rsrc);
        const unsigned w2 = w << ((lane & 7u) * 4u);
        float4 f;
        f.x = __uint_as_float(((unsigned)((int)(w2     ) >> 31)) & 0x3F800000u);
        f.y = __uint_as_float(((unsigned)((int)(w2 << 1) >> 31)) & 0x3F800000u);
        f.z = __uint_as_float(((unsigned)((int)(w2 << 2) >> 31)) & 0x3F800000u);
        f.w = __uint_as_float(((unsigned)((int)(w2 << 3) >> 31)) & 0x3F800000u);
        __stcs(reinterpret_cast<float4*>(
                   po + i * 128 + (lane >> 3) * 32 + (lane & 7u) * 4), f);
    }
}

__global__ void __launch_bounds__(256, 7)
spike_adder_kernel(const uint4* __restrict__ A4,
                   const uint4* __restrict__ B4,
                   float* __restrict__ O,
                   int nwarpTiles, int totalWarps) {
    const int warpId = blockIdx.x * (blockDim.x >> 5) + (threadIdx.x >> 5);
    const unsigned lane = threadIdx.x & 31u;

    for (int t = warpId; t < nwarpTiles; t += totalWarps)
        process_tile(A4, B4, O, t, lane);
}

// Scalar tail kernel (warp-per-row) for nrows % 32 != 0.
__global__ void spike_adder_tail(const float* __restrict__ A,
                                 const float* __restrict__ B,
                                 float* __restrict__ O,
                                 int rowStart, int nrows) {
    const int row = rowStart + blockIdx.x;
    const int lane = threadIdx.x & 31;
    if (row >= nrows) return;
    const size_t base = (size_t)row * 32 + lane;
    const unsigned ua = __ballot_sync(0xFFFFFFFFu, A[base] != 0.0f);
    const unsigned ub = __ballot_sync(0xFFFFFFFFu, B[base] != 0.0f);
    const unsigned res = spike_fp32_add(__brev(ua), __brev(ub));
    const unsigned f = ((unsigned)((int)(res << lane) >> 31)) & 0x3F800000u;
    O[base] = __uint_as_float(f);
}

extern "C" void kernel_launch(void* const* d_in, const int* in_sizes, int n_in,
                              void* d_out, int out_size) {
    const float* A = (const float*)d_in[0];
    const float* B = (const float*)d_in[1];
    float* O = (float*)d_out;

    const int nrows = in_sizes[0] / 32;
    const int nwarpTiles = nrows / 32;
    const int tailRows = nrows - nwarpTiles * 32;

    if (nwarpTiles > 0) {
        const int threads = 256;
        const int warpsPerBlock = threads / 32;         // 8
        const int tilesPerWarp = 2;
        int blocks = (nwarpTiles + warpsPerBlock * tilesPerWarp - 1) /
                     (warpsPerBlock * tilesPerWarp);    // 1024 for N=524288
        const int totalWarps = blocks * warpsPerBlock;
        spike_adder_kernel<<<blocks, threads>>>(
            (const uint4*)A, (const uint4*)B, O, nwarpTiles, totalWarps);
    }
    if (tailRows > 0) {
        spike_adder_tail<<<tailRows, 32>>>(A, B, O, nwarpTiles * 32, nrows);
    }
}